// round 1
// baseline (speedup 1.0000x reference)
#include <cuda_runtime.h>

#define NB 256
#define NC 50000
#define ND 512
#define ALPHA_F 0.5f

// scratch (no allocations allowed)
__device__ int g_labels[NB];
__device__ int g_counts[NC];

// ---------------------------------------------------------------- K0: zero counts
__global__ void k_zero_counts() {
    int i = blockIdx.x * blockDim.x + threadIdx.x;
    if (i < NC) g_counts[i] = 0;
}

// ---------------------------------------------------------------- K1: find labels from onehot
// onehot is [NB, NC] f32, NC % 4 == 0 so every row is float4-aligned.
// Total float4 elements: NB * NC / 4 = 3,200,000. Exact grid, no stride loop.
__global__ void k_find_labels(const float4* __restrict__ onehot) {
    int i = blockIdx.x * blockDim.x + threadIdx.x;   // 0 .. 3,199,999
    float4 v = onehot[i];
    if (v.x != 0.0f || v.y != 0.0f || v.z != 0.0f || v.w != 0.0f) {
        int b = i / (NC / 4);
        int cbase = (i % (NC / 4)) * 4;
        int off = (v.x != 0.0f) ? 0 : (v.y != 0.0f) ? 1 : (v.z != 0.0f) ? 2 : 3;
        int c = cbase + off;
        g_labels[b] = c;                 // unique writer per row
        atomicAdd(&g_counts[c], 1);
    }
}

// ---------------------------------------------------------------- K2: scaled copy of centers
// new_centers[c] = centers[c] * (1 - ALPHA*count/(count+1))
// One block (128 threads) per class row; each thread one float4 (512 floats/row).
__global__ void k_scale_centers(const float4* __restrict__ centers,
                                float4* __restrict__ out_centers) {
    int c = blockIdx.x;
    int cnt = g_counts[c];
    float scale = 1.0f - (ALPHA_F * (float)cnt) / ((float)cnt + 1.0f);
    int idx = c * (ND / 4) + threadIdx.x;
    float4 v = centers[idx];
    v.x *= scale; v.y *= scale; v.z *= scale; v.w *= scale;
    out_centers[idx] = v;
}

// ---------------------------------------------------------------- K3: scatter x-term + distance
// One block (128 threads) per sample.
__global__ void k_scatter_dist(const float* __restrict__ x,
                               const float* __restrict__ centers,
                               float* __restrict__ out_centers,
                               float* __restrict__ result) {
    __shared__ float s_warp[4];
    int b = blockIdx.x;
    int t = threadIdx.x;          // 0..127
    int lab = g_labels[b];
    int cnt = g_counts[lab];
    float inv = ALPHA_F / ((float)cnt + 1.0f);

    const float4* xr = (const float4*)(x + (size_t)b * ND);
    const float4* cr = (const float4*)(centers + (size_t)lab * ND);
    float4 xv = xr[t];
    float4 cv = cr[t];

    // scatter-add ALPHA * x / (cnt+1) onto the already-scaled new_centers row
    float* orow = out_centers + (size_t)lab * ND + t * 4;
    atomicAdd(orow + 0, inv * xv.x);
    atomicAdd(orow + 1, inv * xv.y);
    atomicAdd(orow + 2, inv * xv.z);
    atomicAdd(orow + 3, inv * xv.w);

    // squared distance to OLD center
    float dx = xv.x - cv.x, dy = xv.y - cv.y, dz = xv.z - cv.z, dw = xv.w - cv.w;
    float s = dx * dx + dy * dy + dz * dz + dw * dw;

    // block reduce (4 warps)
    #pragma unroll
    for (int off = 16; off > 0; off >>= 1)
        s += __shfl_down_sync(0xFFFFFFFFu, s, off);
    if ((t & 31) == 0) s_warp[t >> 5] = s;
    __syncthreads();
    if (t == 0)
        result[b] = s_warp[0] + s_warp[1] + s_warp[2] + s_warp[3];
}

// ---------------------------------------------------------------- launch
extern "C" void kernel_launch(void* const* d_in, const int* in_sizes, int n_in,
                              void* d_out, int out_size) {
    const float* x       = (const float*)d_in[0];   // [256, 512]
    const float* onehot  = (const float*)d_in[1];   // [256, 50000]
    const float* centers = (const float*)d_in[2];   // [50000, 512]

    float* result      = (float*)d_out;             // [256]
    float* new_centers = (float*)d_out + NB;        // [50000, 512], 1024B-aligned

    k_zero_counts<<<(NC + 255) / 256, 256>>>();
    k_find_labels<<<(NB * NC / 4) / 256, 256>>>((const float4*)onehot);
    k_scale_centers<<<NC, ND / 4>>>((const float4*)centers, (float4*)new_centers);
    k_scatter_dist<<<NB, ND / 4>>>(x, centers, new_centers, result);
}

// round 2
// speedup vs baseline: 1.0287x; 1.0287x over previous
#include <cuda_runtime.h>

#define NB 256
#define NC 50000
#define ND 512
#define ALPHA_F 0.5f

// ---------------------------------------------------------------- scratch
__device__ int   g_labels[NB];
__device__ int   g_counts[NC];
__device__ int   g_slot[NC];          // class -> compact slot (valid only if count>0)
__device__ int   g_nslots;
__device__ float g_xsum[NB * ND];     // per-slot accumulated x (512 KB)

// ---------------------------------------------------------------- K0: zero scratch
__global__ void k_zero() {
    int i = blockIdx.x * blockDim.x + threadIdx.x;
    if (i < NC) g_counts[i] = 0;
    if (i < NB * ND) g_xsum[i] = 0.0f;
    if (i == 0) g_nslots = 0;
}

// ---------------------------------------------------------------- K1: labels, counts, slots
// onehot is [NB, NC] f32; scan as float4 (NC % 4 == 0). 3.2M float4s, exact grid.
__global__ void k_find_labels(const float4* __restrict__ onehot) {
    int i = blockIdx.x * blockDim.x + threadIdx.x;   // 0 .. 3,199,999
    float4 v = onehot[i];
    if (v.x != 0.0f || v.y != 0.0f || v.z != 0.0f || v.w != 0.0f) {
        int b = i / (NC / 4);
        int cbase = (i % (NC / 4)) * 4;
        int off = (v.x != 0.0f) ? 0 : (v.y != 0.0f) ? 1 : (v.z != 0.0f) ? 2 : 3;
        int c = cbase + off;
        g_labels[b] = c;                              // unique writer per row b
        int old = atomicAdd(&g_counts[c], 1);
        if (old == 0)                                 // first toucher assigns slot
            g_slot[c] = atomicAdd(&g_nslots, 1);
    }
}

// ---------------------------------------------------------------- K1c: per-sample xsum + distance
// One block (128 threads) per sample. Accumulates x into slot-indexed scratch
// (collisions only between samples sharing a class — rare) and computes
// result[b] = ||x[b] - centers[label[b]]||^2 against OLD centers.
__global__ void k_sample(const float* __restrict__ x,
                         const float* __restrict__ centers,
                         float* __restrict__ result) {
    __shared__ float s_warp[4];
    int b = blockIdx.x;
    int t = threadIdx.x;              // 0..127
    int lab  = g_labels[b];
    int slot = g_slot[lab];

    float4 xv = ((const float4*)(x + (size_t)b * ND))[t];
    float4 cv = ((const float4*)(centers + (size_t)lab * ND))[t];

    float* xs = g_xsum + (size_t)slot * ND + t * 4;
    atomicAdd(xs + 0, xv.x);
    atomicAdd(xs + 1, xv.y);
    atomicAdd(xs + 2, xv.z);
    atomicAdd(xs + 3, xv.w);

    float dx = xv.x - cv.x, dy = xv.y - cv.y, dz = xv.z - cv.z, dw = xv.w - cv.w;
    float s = dx * dx + dy * dy + dz * dz + dw * dw;
    #pragma unroll
    for (int off = 16; off > 0; off >>= 1)
        s += __shfl_down_sync(0xFFFFFFFFu, s, off);
    if ((t & 31) == 0) s_warp[t >> 5] = s;
    __syncthreads();
    if (t == 0)
        result[b] = s_warp[0] + s_warp[1] + s_warp[2] + s_warp[3];
}

// ---------------------------------------------------------------- K2: single fused output pass
// new_centers[c] = centers[c] * (1 - a*cnt/(cnt+1)) + (a/(cnt+1)) * xsum[slot[c]]
// One block (128 threads) per class row, float4 per thread. For the ~49.7K
// untouched classes this is a pure scaled copy (scale = 1).
__global__ void k_centers(const float4* __restrict__ centers,
                          float4* __restrict__ out_centers) {
    int c = blockIdx.x;
    int cnt = g_counts[c];
    float fc    = (float)cnt;
    float inv   = ALPHA_F / (fc + 1.0f);
    float scale = 1.0f - inv * fc;

    int idx = c * (ND / 4) + threadIdx.x;
    float4 v = centers[idx];
    if (cnt > 0) {
        float4 s = ((const float4*)g_xsum)[g_slot[c] * (ND / 4) + threadIdx.x];
        v.x = v.x * scale + inv * s.x;
        v.y = v.y * scale + inv * s.y;
        v.z = v.z * scale + inv * s.z;
        v.w = v.w * scale + inv * s.w;
    } else {
        v.x *= scale; v.y *= scale; v.z *= scale; v.w *= scale;
    }
    out_centers[idx] = v;
}

// ---------------------------------------------------------------- launch
extern "C" void kernel_launch(void* const* d_in, const int* in_sizes, int n_in,
                              void* d_out, int out_size) {
    const float* x       = (const float*)d_in[0];   // [256, 512]
    const float* onehot  = (const float*)d_in[1];   // [256, 50000]
    const float* centers = (const float*)d_in[2];   // [50000, 512]

    float* result      = (float*)d_out;             // [256]
    float* new_centers = (float*)d_out + NB;        // [50000, 512]

    k_zero<<<(NB * ND + 255) / 256, 256>>>();                     // covers NC too? NB*ND=131072 > NC=50000 ✔
    k_find_labels<<<(NB * NC / 4) / 256, 256>>>((const float4*)onehot);
    k_sample<<<NB, ND / 4>>>(x, centers, result);
    k_centers<<<NC, ND / 4>>>((const float4*)centers, (float4*)new_centers);
}